// round 5
// baseline (speedup 1.0000x reference)
#include <cuda_runtime.h>
#include <cuda_bf16.h>
#include <cstdint>

// 4096-pt FWHT, 8192 rows fp32.
// Radix 64x64: Round A butterflies element bits [7:2], Round B bits {[11:8],[1:0]}.
// One 64-thread CTA streams rows_per_cta rows through 2 smem buffers with
// cp.async.cg. 2 barriers per row: the post-wait barrier doubles as the
// write-after-read guard for the buffer the upcoming prefetch overwrites.
// Skewed smem (phys = e + (e>>8)*4): all access patterns bank-conflict-free.
// Packed fma.rn.f32x2 butterflies; coalesced LDGSTS / STG.128 (.cs).

#define ROW    4096
#define TPR    64            // threads per CTA (= per row)
#define SROW   4160          // skewed row words (max phys 4155, pad to 16B mult)
#define NCTAS  1024

__device__ __forceinline__ float2 ffma2(float2 b, float2 m, float2 a) {
    float2 r;
    asm("fma.rn.f32x2 %0, %1, %2, %3;"
        : "=l"(reinterpret_cast<unsigned long long&>(r))
        : "l"(reinterpret_cast<const unsigned long long&>(b)),
          "l"(reinterpret_cast<const unsigned long long&>(m)),
          "l"(reinterpret_cast<const unsigned long long&>(a)));
    return r;
}

__device__ __forceinline__ float2 fmul2(float2 a, float2 m) {
    float2 r;
    asm("mul.rn.f32x2 %0, %1, %2;"
        : "=l"(reinterpret_cast<unsigned long long&>(r))
        : "l"(reinterpret_cast<const unsigned long long&>(a)),
          "l"(reinterpret_cast<const unsigned long long&>(m)));
    return r;
}

// 64-pt FWHT over 32 packed float2 (v[p] = (elem 2p, elem 2p+1)).
__device__ __forceinline__ void fwht64p(float2* v) {
    const float2 P1 = make_float2(1.0f, 1.0f);
    const float2 M1 = make_float2(-1.0f, -1.0f);
#pragma unroll
    for (int p = 0; p < 32; p++) {           // h=1 (intra-pair)
        float lo = v[p].x, hi = v[p].y;
        v[p].x = lo + hi;
        v[p].y = lo - hi;
    }
#pragma unroll
    for (int h = 1; h < 32; h <<= 1) {       // h=2..64 packed
#pragma unroll
        for (int p = 0; p < 32; p++) {
            if ((p & h) == 0) {
                float2 a = v[p], b = v[p + h];
                v[p]     = ffma2(b, P1, a);
                v[p + h] = ffma2(b, M1, a);
            }
        }
    }
}

__device__ __forceinline__ void cp_async16(uint32_t dst_smem, const void* src) {
    asm volatile("cp.async.cg.shared.global [%0], [%1], 16;"
                 :: "r"(dst_smem), "l"(src) : "memory");
}
__device__ __forceinline__ void cp_commit() {
    asm volatile("cp.async.commit_group;" ::: "memory");
}
__device__ __forceinline__ void cp_wait_all() {
    asm volatile("cp.async.wait_group 0;" ::: "memory");
}

__device__ __forceinline__ void stg128_cs(float4* dst, float4 v) {
    asm volatile("st.global.cs.v4.f32 [%0], {%1, %2, %3, %4};"
                 :: "l"(dst), "f"(v.x), "f"(v.y), "f"(v.z), "f"(v.w) : "memory");
}

// Stage one row into a smem buffer: float4 q = i*64 + t (coalesced),
// element e = 256*i + 4*t -> skewed word 260*i + 4*t (16B aligned).
__device__ __forceinline__ void stage_row(uint32_t sbuf, const float4* x4, int t) {
#pragma unroll
    for (int i = 0; i < 16; i++)
        cp_async16(sbuf + (260u * i + 4u * t) * 4u, x4 + i * 64 + t);
    cp_commit();
}

__global__ void __launch_bounds__(TPR)
fwht4096_kernel(const float* __restrict__ in, float* __restrict__ out, int rows_per_cta) {
    __shared__ __align__(16) float s[2 * SROW];

    const int t = threadIdx.x;
    const long row0 = (long)blockIdx.x * rows_per_cta;

    uint32_t sbase;
    asm("{ .reg .u64 tmp; cvta.to.shared.u64 tmp, %1; cvt.u32.u64 %0, tmp; }"
        : "=r"(sbase) : "l"(s));
    const uint32_t sbuf0 = sbase;
    const uint32_t sbuf1 = sbase + SROW * 4u;

    // Prologue: prefetch row 0 into buffer 0.
    stage_row(sbuf0, reinterpret_cast<const float4*>(in + row0 * ROW), t);

    const int j = t >> 2, r = t & 3;   // round-A ownership

    for (int k = 0; k < rows_per_cta; k++) {
        const int cur = k & 1;
        float* sm = s + cur * SROW;

        // Row k's group is the only pending one (row k+1 issued below).
        cp_wait_all();
        // Barrier 1: (a) makes all threads' cp.async data for row k visible,
        // (b) orders last iteration's round-B reads of buf[cur^1] before the
        // prefetch below overwrites it.
        __syncthreads();

        // ---- Round A gathers (LDS first, then overlap LDGSTS issue).
        float2 v[32];
        {
            const float* base = sm + 260 * j + r;
#pragma unroll
            for (int p = 0; p < 32; p++)
                v[p] = make_float2(base[8 * p], base[8 * p + 4]);
        }

        // Prefetch row k+1 into the other buffer; issue overlaps round A math.
        if (k + 1 < rows_per_cta)
            stage_row(cur ? sbuf0 : sbuf1,
                      reinterpret_cast<const float4*>(in + (row0 + k + 1) * ROW), t);

        // ---- Round A: butterflies element bits [7:2]; scatter to self-owned
        // addresses (no barrier needed before the writes).
        fwht64p(v);
        {
            float* base = sm + 260 * j + r;
#pragma unroll
            for (int p = 0; p < 32; p++) {
                base[8 * p]     = v[p].x;
                base[8 * p + 4] = v[p].y;
            }
        }
        __syncthreads();   // Barrier 2: round A scatter -> round B gather

        // ---- Round B: thread t owns e = jj*256 + 4*t + rr (LDS.128 gather),
        // butterflies bits {[11:8],[1:0]}, then scaled streaming STG.128.
        {
            float2 w[32];
#pragma unroll
            for (int jj = 0; jj < 16; jj++) {
                float4 q = *reinterpret_cast<const float4*>(sm + 260 * jj + 4 * t);
                w[2 * jj]     = make_float2(q.x, q.y);
                w[2 * jj + 1] = make_float2(q.z, q.w);
            }
            fwht64p(w);

            const float2 SC = make_float2(1.0f / 64.0f, 1.0f / 64.0f);
            float4* y4 = reinterpret_cast<float4*>(out + (row0 + k) * ROW);
#pragma unroll
            for (int jj = 0; jj < 16; jj++) {
                float2 lo = fmul2(w[2 * jj], SC);
                float2 hi = fmul2(w[2 * jj + 1], SC);
                float4 o;
                o.x = lo.x; o.y = lo.y; o.z = hi.x; o.w = hi.y;
                stg128_cs(y4 + jj * 64 + t, o);
            }
        }
        // No trailing barrier: next iteration's barrier-1 protects buf[cur].
    }
}

extern "C" void kernel_launch(void* const* d_in, const int* in_sizes, int n_in,
                              void* d_out, int out_size) {
    const float* x = (const float*)d_in[0];
    float* y = (float*)d_out;
    int total = in_sizes[0];
    int nrows = total / ROW;                      // 8192
    int nctas = NCTAS;
    if (nrows % nctas != 0) nctas = nrows;        // fallback: 1 row per CTA
    int rpc = nrows / nctas;
    fwht4096_kernel<<<nctas, TPR>>>(x, y, rpc);
}

// round 6
// speedup vs baseline: 1.1129x; 1.1129x over previous
#include <cuda_runtime.h>
#include <cuda_bf16.h>
#include <cstdint>

// 4096-pt FWHT, 8192 rows fp32.
// Radix 64x64: Round A butterflies element bits [7:2], Round B bits {[11:8],[1:0]}.
// One 64-thread CTA streams rows through a 3-buffer smem ring with cp.async.cg,
// prefetch distance 2 (row k+2 issued before waiting on row k). R4-proven
// ordering: stage -> wait -> barrier -> compute. Skewed smem
// (phys = e + (e>>8)*4): every access pattern bank-conflict-free.
// Packed fma.rn.f32x2 butterflies; coalesced LDGSTS / LDS.128 / STG.128.

#define ROW    4096
#define TPR    64            // threads per CTA (= per row)
#define SROW   4160          // skewed row words (max phys 4155, pad to 16B mult)
#define NBUF   3
#define NCTAS  1024

__device__ __forceinline__ float2 ffma2(float2 b, float2 m, float2 a) {
    float2 r;
    asm("fma.rn.f32x2 %0, %1, %2, %3;"
        : "=l"(reinterpret_cast<unsigned long long&>(r))
        : "l"(reinterpret_cast<const unsigned long long&>(b)),
          "l"(reinterpret_cast<const unsigned long long&>(m)),
          "l"(reinterpret_cast<const unsigned long long&>(a)));
    return r;
}

__device__ __forceinline__ float2 fmul2(float2 a, float2 m) {
    float2 r;
    asm("mul.rn.f32x2 %0, %1, %2;"
        : "=l"(reinterpret_cast<unsigned long long&>(r))
        : "l"(reinterpret_cast<const unsigned long long&>(a)),
          "l"(reinterpret_cast<const unsigned long long&>(m)));
    return r;
}

// 64-pt FWHT over 32 packed float2 (v[p] = (elem 2p, elem 2p+1)).
__device__ __forceinline__ void fwht64p(float2* v) {
    const float2 P1 = make_float2(1.0f, 1.0f);
    const float2 M1 = make_float2(-1.0f, -1.0f);
#pragma unroll
    for (int p = 0; p < 32; p++) {           // h=1 (intra-pair)
        float lo = v[p].x, hi = v[p].y;
        v[p].x = lo + hi;
        v[p].y = lo - hi;
    }
#pragma unroll
    for (int h = 1; h < 32; h <<= 1) {       // h=2..64 packed
#pragma unroll
        for (int p = 0; p < 32; p++) {
            if ((p & h) == 0) {
                float2 a = v[p], b = v[p + h];
                v[p]     = ffma2(b, P1, a);
                v[p + h] = ffma2(b, M1, a);
            }
        }
    }
}

__device__ __forceinline__ void cp_async16(uint32_t dst_smem, const void* src) {
    asm volatile("cp.async.cg.shared.global [%0], [%1], 16;"
                 :: "r"(dst_smem), "l"(src) : "memory");
}
__device__ __forceinline__ void cp_commit() {
    asm volatile("cp.async.commit_group;" ::: "memory");
}
template <int N>
__device__ __forceinline__ void cp_wait() {
    asm volatile("cp.async.wait_group %0;" :: "n"(N) : "memory");
}

// Stage one row into a smem buffer: float4 q = i*64 + t (coalesced),
// element e = 256*i + 4*t -> skewed word 260*i + 4*t (16B aligned).
__device__ __forceinline__ void stage_row(uint32_t sbuf, const float4* x4, int t) {
#pragma unroll
    for (int i = 0; i < 16; i++)
        cp_async16(sbuf + (260u * i + 4u * t) * 4u, x4 + i * 64 + t);
    cp_commit();
}

__global__ void __launch_bounds__(TPR)
fwht4096_kernel(const float* __restrict__ in, float* __restrict__ out, int rows_per_cta) {
    __shared__ __align__(16) float s[NBUF * SROW];

    const int t = threadIdx.x;
    const long row0 = (long)blockIdx.x * rows_per_cta;

    uint32_t sbase;
    asm("{ .reg .u64 tmp; cvta.to.shared.u64 tmp, %1; cvt.u32.u64 %0, tmp; }"
        : "=r"(sbase) : "l"(s));

    // Prologue: prefetch rows 0 and 1 (each its own commit group, issued in order).
    stage_row(sbase + 0 * SROW * 4u,
              reinterpret_cast<const float4*>(in + row0 * ROW), t);
    if (rows_per_cta > 1)
        stage_row(sbase + 1 * SROW * 4u,
                  reinterpret_cast<const float4*>(in + (row0 + 1) * ROW), t);

    const int j = t >> 2, r = t & 3;   // round-A ownership
    int cur = 0;                        // k % NBUF

    for (int k = 0; k < rows_per_cta; k++) {
        // Prefetch row k+2 into buf[(k+2)%NBUF] (last read in iteration k-1;
        // iteration k-1's trailing barrier protects it).
        const int pre = (cur + 2 < NBUF) ? cur + 2 : cur + 2 - NBUF;
        if (k + 2 < rows_per_cta)
            stage_row(sbase + (uint32_t)pre * SROW * 4u,
                      reinterpret_cast<const float4*>(in + (row0 + k + 2) * ROW), t);

        // Wait until row k's group is complete: newer pending groups remain.
        const int rem = rows_per_cta - 1 - k;
        if (rem >= 2)      cp_wait<2>();
        else if (rem == 1) cp_wait<1>();
        else               cp_wait<0>();
        __syncthreads();   // data visible to all threads

        float* sm = s + cur * SROW;

        // ---- Round A: thread (j,r) owns e = j*256 + m*4 + r, m = 0..63.
        // Skewed word = 260*j + 4*m + r; banks (4j+r) mod 32 per phase -> clean.
        {
            float* base = sm + 260 * j + r;
            float2 v[32];
#pragma unroll
            for (int p = 0; p < 32; p++)
                v[p] = make_float2(base[8 * p], base[8 * p + 4]);
            fwht64p(v);   // butterflies bits [7:2]
#pragma unroll
            for (int p = 0; p < 32; p++) {
                base[8 * p]     = v[p].x;
                base[8 * p + 4] = v[p].y;
            }
        }
        __syncthreads();   // round A scatter -> round B gather

        // ---- Round B: thread t owns e = jj*256 + 4*t + rr (LDS.128 gather),
        // butterflies bits {[11:8],[1:0]}, then scaled coalesced STG.128.
        {
            float2 w[32];
#pragma unroll
            for (int jj = 0; jj < 16; jj++) {
                float4 q = *reinterpret_cast<const float4*>(sm + 260 * jj + 4 * t);
                w[2 * jj]     = make_float2(q.x, q.y);
                w[2 * jj + 1] = make_float2(q.z, q.w);
            }
            fwht64p(w);

            const float2 SC = make_float2(1.0f / 64.0f, 1.0f / 64.0f);
            float4* y4 = reinterpret_cast<float4*>(out + (row0 + k) * ROW);
#pragma unroll
            for (int jj = 0; jj < 16; jj++) {
                float2 lo = fmul2(w[2 * jj], SC);
                float2 hi = fmul2(w[2 * jj + 1], SC);
                float4 o;
                o.x = lo.x; o.y = lo.y; o.z = hi.x; o.w = hi.y;
                y4[jj * 64 + t] = o;
            }
        }
        // Trailing barrier: protects buf[cur] (and the buffer the next
        // iteration's prefetch overwrites) against early re-write.
        __syncthreads();

        cur = (cur + 1 < NBUF) ? cur + 1 : 0;
    }
}

extern "C" void kernel_launch(void* const* d_in, const int* in_sizes, int n_in,
                              void* d_out, int out_size) {
    const float* x = (const float*)d_in[0];
    float* y = (float*)d_out;
    int total = in_sizes[0];
    int nrows = total / ROW;                      // 8192
    int nctas = NCTAS;
    if (nrows % nctas != 0) nctas = nrows;        // fallback: 1 row per CTA
    int rpc = nrows / nctas;
    fwht4096_kernel<<<nctas, TPR>>>(x, y, rpc);
}